// round 1
// baseline (speedup 1.0000x reference)
#include <cuda_runtime.h>
#include <math.h>

#define NB 16
#define NT 256
#define NC 64
#define NF 128
#define NGO 32
#define NH 32
#define TCHUNK 8

// ---------------- scratch (device globals; no allocation) ----------------
__device__ float g_sm[NC * NF];                 // softmax(spectral_w)
__device__ float g_A[NB * NC * NC];             // accumulated (unscaled) adjacency
__device__ unsigned char g_amask[NB * NC * NC]; // GAT attention mask
__device__ float g_Wh[NB * NT * NC * NGO];      // 33.5 MB
__device__ float g_s1[NB * NT * NC];
__device__ float g_s2[NB * NT * NC];
__device__ float g_hp[NB * NT * NH];            // pooled node features
__device__ float g_gx[2 * NB * NT * 4 * NH];    // LSTM input-gate precompute
__device__ float g_hl[NB * NT * 2 * NH];        // biLSTM output (concat)

// ---------------- kernel 0: row softmax of spectral_w ----------------
__global__ void k_sm(const float* __restrict__ sw) {
    int c = blockIdx.x;          // 64
    int f = threadIdx.x;         // 128
    float v = sw[c * NF + f];
    __shared__ float rm[4], rs[4];
    int lane = f & 31, w = f >> 5;
    float m = v;
#pragma unroll
    for (int o = 16; o; o >>= 1) m = fmaxf(m, __shfl_xor_sync(0xffffffffu, m, o));
    if (lane == 0) rm[w] = m;
    __syncthreads();
    m = fmaxf(fmaxf(rm[0], rm[1]), fmaxf(rm[2], rm[3]));
    float e = __expf(v - m);
    float s = e;
#pragma unroll
    for (int o = 16; o; o >>= 1) s += __shfl_xor_sync(0xffffffffu, s, o);
    if (lane == 0) rs[w] = s;
    __syncthreads();
    s = rs[0] + rs[1] + rs[2] + rs[3];
    g_sm[c * NF + f] = e / s;
}

__global__ void k_zeroA() {
    int i = blockIdx.x * blockDim.x + threadIdx.x;
    if (i < NB * NC * NC) g_A[i] = 0.0f;
}

// ---------------- kernel 1: spectral weight + Gram->A + Wh + s1/s2 ----------------
// grid = NB * (NT/TCHUNK) = 512 blocks, 256 threads
// dynamic smem: xw[64][132] + sw[128][32] + invn[64]
extern __shared__ float sh1[];
__global__ void k1(const float* __restrict__ x,
                   const float* __restrict__ gatW,
                   const float* __restrict__ gata) {
    float* xw   = sh1;                    // 64*132
    float* sw   = sh1 + 64 * 132;         // 128*32
    float* invn = sw + 128 * 32;          // 64

    const int b  = blockIdx.x / (NT / TCHUNK);
    const int t0 = (blockIdx.x % (NT / TCHUNK)) * TCHUNK;
    const int tid = threadIdx.x;

    for (int i = tid; i < NF * NGO; i += 256) sw[i] = gatW[i];

    // triangle 4x4-tile mapping over 16x16 tiles: tiles with di>=ci (136 of 256)
    int ci = -1, di = -1;
    {
        int u = tid;
        for (int r = 0; r < 16; r++) {
            int len = 16 - r;
            if (u < len) { ci = r; di = r + u; break; }
            u -= len;
        }
        if (tid >= 136) { ci = -1; }
    }
    const int r0 = (ci >= 0) ? ci * 4 : 0;
    const int c0 = (ci >= 0) ? di * 4 : 0;

    const int cW = tid >> 2, q = tid & 3, o0 = q * 8;
    float ga1[8], ga2[8];
#pragma unroll
    for (int i = 0; i < 8; i++) { ga1[i] = gata[o0 + i]; ga2[i] = gata[NGO + o0 + i]; }

    float acc[16];
#pragma unroll
    for (int i = 0; i < 16; i++) acc[i] = 0.0f;

    for (int tt = 0; tt < TCHUNK; tt++) {
        const int t = t0 + tt;
        const float* xp = x + ((size_t)(b * NT + t)) * NC * NF;
        __syncthreads();   // previous iteration done with xw
        // load + spectral weight (float4)
        for (int i = tid * 4; i < NC * NF; i += 1024) {
            float4 v = *(const float4*)(xp + i);
            float4 s = *(const float4*)(g_sm + i);
            int c = i >> 7, f = i & 127;
            float* dst = &xw[c * 132 + f];
            dst[0] = v.x * s.x; dst[1] = v.y * s.y; dst[2] = v.z * s.z; dst[3] = v.w * s.w;
        }
        __syncthreads();
        // norms (threads 0..63)
        if (tid < 64) {
            float s = 0.0f;
            const float* row = &xw[tid * 132];
#pragma unroll 4
            for (int f = 0; f < NF; f += 4) {
                float4 a = *(const float4*)(row + f);
                s += a.x * a.x + a.y * a.y + a.z * a.z + a.w * a.w;
            }
            invn[tid] = 1.0f / (sqrtf(s) + 1e-8f);
        }
        // Wh: all 256 threads, thread = (cW, o0..o0+7)
        {
            float wa[8];
#pragma unroll
            for (int i = 0; i < 8; i++) wa[i] = 0.0f;
            const float* xrow = &xw[cW * 132];
#pragma unroll 4
            for (int f = 0; f < NF; f++) {
                float xv = xrow[f];
                float4 w0 = *(const float4*)&sw[f * NGO + o0];
                float4 w1 = *(const float4*)&sw[f * NGO + o0 + 4];
                wa[0] += xv * w0.x; wa[1] += xv * w0.y; wa[2] += xv * w0.z; wa[3] += xv * w0.w;
                wa[4] += xv * w1.x; wa[5] += xv * w1.y; wa[6] += xv * w1.z; wa[7] += xv * w1.w;
            }
            float* whp = g_Wh + (((size_t)(b * NT + t) * NC + cW) * NGO + o0);
            *(float4*)whp       = make_float4(wa[0], wa[1], wa[2], wa[3]);
            *(float4*)(whp + 4) = make_float4(wa[4], wa[5], wa[6], wa[7]);
            float p1 = 0.0f, p2 = 0.0f;
#pragma unroll
            for (int i = 0; i < 8; i++) { p1 += wa[i] * ga1[i]; p2 += wa[i] * ga2[i]; }
            p1 += __shfl_xor_sync(0xffffffffu, p1, 1);
            p1 += __shfl_xor_sync(0xffffffffu, p1, 2);
            p2 += __shfl_xor_sync(0xffffffffu, p2, 1);
            p2 += __shfl_xor_sync(0xffffffffu, p2, 2);
            if (q == 0) {
                g_s1[(size_t)(b * NT + t) * NC + cW] = p1;
                g_s2[(size_t)(b * NT + t) * NC + cW] = p2;
            }
        }
        __syncthreads();   // invn ready, Wh reads of xw done (gram also reads xw, same data)
        // Gram tile (threads with a triangle tile)
        if (ci >= 0) {
            float tm[16];
#pragma unroll
            for (int i = 0; i < 16; i++) tm[i] = 0.0f;
            for (int k = 0; k < NF; k += 4) {
                float4 a0 = *(const float4*)&xw[(r0 + 0) * 132 + k];
                float4 a1 = *(const float4*)&xw[(r0 + 1) * 132 + k];
                float4 a2 = *(const float4*)&xw[(r0 + 2) * 132 + k];
                float4 a3 = *(const float4*)&xw[(r0 + 3) * 132 + k];
                float4 b0 = *(const float4*)&xw[(c0 + 0) * 132 + k];
                float4 b1 = *(const float4*)&xw[(c0 + 1) * 132 + k];
                float4 b2 = *(const float4*)&xw[(c0 + 2) * 132 + k];
                float4 b3 = *(const float4*)&xw[(c0 + 3) * 132 + k];
#define DOT4(A_, B_) (A_.x * B_.x + A_.y * B_.y + A_.z * B_.z + A_.w * B_.w)
                tm[0]  += DOT4(a0, b0); tm[1]  += DOT4(a0, b1); tm[2]  += DOT4(a0, b2); tm[3]  += DOT4(a0, b3);
                tm[4]  += DOT4(a1, b0); tm[5]  += DOT4(a1, b1); tm[6]  += DOT4(a1, b2); tm[7]  += DOT4(a1, b3);
                tm[8]  += DOT4(a2, b0); tm[9]  += DOT4(a2, b1); tm[10] += DOT4(a2, b2); tm[11] += DOT4(a2, b3);
                tm[12] += DOT4(a3, b0); tm[13] += DOT4(a3, b1); tm[14] += DOT4(a3, b2); tm[15] += DOT4(a3, b3);
#undef DOT4
            }
            float ir[4], ic[4];
#pragma unroll
            for (int i = 0; i < 4; i++) { ir[i] = invn[r0 + i]; ic[i] = invn[c0 + i]; }
#pragma unroll
            for (int r = 0; r < 4; r++)
#pragma unroll
                for (int cc = 0; cc < 4; cc++)
                    acc[r * 4 + cc] += tm[r * 4 + cc] * ir[r] * ic[cc];
        }
    }
    // flush accumulated Gram to A
    if (ci >= 0) {
        float* Ab = g_A + b * NC * NC;
#pragma unroll
        for (int r = 0; r < 4; r++)
#pragma unroll
            for (int cc = 0; cc < 4; cc++) {
                float v = acc[r * 4 + cc];
                atomicAdd(&Ab[(r0 + r) * NC + (c0 + cc)], v);
                if (ci != di) atomicAdd(&Ab[(c0 + cc) * NC + (r0 + r)], v);
            }
    }
}

// ---------------- kernel 2: top-(K+1), symmetrize, build amask ----------------
__global__ void k2() {  // grid NB, 64 threads
    const int b = blockIdx.x, c = threadIdx.x;
    const float* Ab = g_A + b * NC * NC;
    __shared__ unsigned long long um[NC];
    float bv[4]; int bi[4];
#pragma unroll
    for (int j = 0; j < 4; j++) { bv[j] = -3.4e38f; bi[j] = 0; }
    for (int d = 0; d < NC; d++) {
        float a = Ab[c * NC + d];
        if (a > bv[3]) {
            int p = 3;
            // find insert position (strict >, ties keep earlier index first)
            while (p > 0 && a > bv[p - 1]) p--;
            for (int j = 3; j > p; j--) { bv[j] = bv[j - 1]; bi[j] = bi[j - 1]; }
            bv[p] = a; bi[p] = d;
        }
    }
    unsigned long long m = 0;
#pragma unroll
    for (int j = 0; j < 4; j++) m |= 1ull << bi[j];
    m &= ~(1ull << c);  // remove diagonal
    um[c] = m;
    __syncthreads();
    unsigned char* amp = g_amask + (size_t)b * NC * NC + c * NC;
    unsigned long long mc = um[c];
    for (int d = 0; d < NC; d++) {
        bool tk = ((mc >> d) & 1ull) || ((um[d] >> c) & 1ull);
        bool am = (tk && Ab[c * NC + d] > 0.0f) || (d == c);
        amp[d] = am ? 1 : 0;
    }
}

// ---------------- kernel 3: GAT attention + node pooling ----------------
// grid NB*NT = 4096 blocks, 256 threads
__global__ void k3(const float* __restrict__ pool_w, const float* __restrict__ pool_b) {
    __shared__ __align__(16) float sWh[NC * NGO];   // 8 KB
    __shared__ float sp[NC * 65];                   // exp(e - max), padded
    __shared__ float sgat[NC * 33];                 // padded
    __shared__ float ss1[NC], ss2[NC], rinv[NC], pnum[NC];
    __shared__ float pw[NGO];
    __shared__ unsigned int samw[NC * NC / 4];
    unsigned char* sam = (unsigned char*)samw;

    const int bt = blockIdx.x;
    const int b = bt >> 8;
    const int tid = threadIdx.x;

    const float* whp = g_Wh + (size_t)bt * NC * NGO;
    for (int i = tid; i < NC * NGO; i += 256) sWh[i] = whp[i];
    if (tid < NC) {
        ss1[tid] = g_s1[(size_t)bt * NC + tid];
        ss2[tid] = g_s2[(size_t)bt * NC + tid];
    }
    const unsigned int* amp = (const unsigned int*)(g_amask + (size_t)b * NC * NC);
    for (int i = tid; i < NC * NC / 4; i += 256) samw[i] = amp[i];
    if (tid < NGO) pw[tid] = pool_w[tid];
    __syncthreads();

    const int c = tid >> 2, q = tid & 3, d0 = q * 16;
    // phase A: e + masked row softmax (4 threads per row)
    float ev[16];
    float m = -3.4e38f;
    const float s1c = ss1[c];
#pragma unroll
    for (int i = 0; i < 16; i++) {
        int d = d0 + i;
        float e = s1c + ss2[d];
        e = (e >= 0.0f) ? e : 0.2f * e;
        if (!sam[c * NC + d]) e = -1e9f;
        ev[i] = e;
        m = fmaxf(m, e);
    }
    m = fmaxf(m, __shfl_xor_sync(0xffffffffu, m, 1));
    m = fmaxf(m, __shfl_xor_sync(0xffffffffu, m, 2));
    float s = 0.0f;
#pragma unroll
    for (int i = 0; i < 16; i++) {
        float p = __expf(ev[i] - m);
        sp[c * 65 + d0 + i] = p;
        s += p;
    }
    s += __shfl_xor_sync(0xffffffffu, s, 1);
    s += __shfl_xor_sync(0xffffffffu, s, 2);
    if (q == 0) rinv[c] = 1.0f / s;
    __syncthreads();

    // phase B: gat = relu(alpha @ Wh), thread = (c, o0..o0+7)
    const int o0 = q * 8;
    float a8[8];
#pragma unroll
    for (int i = 0; i < 8; i++) a8[i] = 0.0f;
    for (int d = 0; d < NC; d++) {
        float al = sp[c * 65 + d];
        float4 w0 = *(const float4*)&sWh[d * NGO + o0];
        float4 w1 = *(const float4*)&sWh[d * NGO + o0 + 4];
        a8[0] += al * w0.x; a8[1] += al * w0.y; a8[2] += al * w0.z; a8[3] += al * w0.w;
        a8[4] += al * w1.x; a8[5] += al * w1.y; a8[6] += al * w1.z; a8[7] += al * w1.w;
    }
    const float ri = rinv[c];
#pragma unroll
    for (int i = 0; i < 8; i++) {
        float g = a8[i] * ri;
        sgat[c * 33 + o0 + i] = (g > 0.0f) ? g : 0.0f;
    }
    __syncthreads();

    // phase C: pooling
    if (tid < NC) {
        float p = pool_b[0];
#pragma unroll
        for (int o = 0; o < NGO; o++) p += sgat[tid * 33 + o] * pw[o];
        pnum[tid] = p;
    }
    __syncthreads();
    if (tid < 32) {
        float a0 = pnum[tid], a1 = pnum[tid + 32];
        float mx = fmaxf(a0, a1);
#pragma unroll
        for (int o = 16; o; o >>= 1) mx = fmaxf(mx, __shfl_xor_sync(0xffffffffu, mx, o));
        float e0 = __expf(a0 - mx), e1 = __expf(a1 - mx);
        float sm = e0 + e1;
#pragma unroll
        for (int o = 16; o; o >>= 1) sm += __shfl_xor_sync(0xffffffffu, sm, o);
        pnum[tid] = e0 / sm;
        pnum[tid + 32] = e1 / sm;
    }
    __syncthreads();
    if (tid < NGO) {
        float hv = 0.0f;
#pragma unroll 4
        for (int c2 = 0; c2 < NC; c2++) hv += sgat[c2 * 33 + tid] * pnum[c2];
        g_hp[(size_t)bt * NH + tid] = hv;
    }
}

// ---------------- kernel 4a: LSTM input gates gx = h@Wi + b ----------------
__global__ void k4a(const float* __restrict__ Wi_f, const float* __restrict__ b_f,
                    const float* __restrict__ Wi_r, const float* __restrict__ b_r) {
    // grid 2*NB*NT = 8192 blocks, 128 threads
    const int id = blockIdx.x;
    const int dir = id >> 12;
    const int bt = id & 4095;
    const float* Wi = dir ? Wi_r : Wi_f;
    const float* bias = dir ? b_r : b_f;
    __shared__ float hr[NH];
    if (threadIdx.x < NH) hr[threadIdx.x] = g_hp[(size_t)bt * NH + threadIdx.x];
    __syncthreads();
    const int j = threadIdx.x;
    float a = bias[j];
#pragma unroll
    for (int k = 0; k < NH; k++) a += hr[k] * Wi[k * 128 + j];
    g_gx[((size_t)dir * 4096 + bt) * 128 + j] = a;
}

// ---------------- kernel 4b: LSTM recurrence ----------------
__global__ void k4b(const float* __restrict__ Wh_f, const float* __restrict__ Wh_r) {
    // grid 32 = (dir*16 + b), 128 threads
    const int dir = blockIdx.x >> 4;
    const int b = blockIdx.x & 15;
    const float* Wh = dir ? Wh_r : Wh_f;
    const int j = threadIdx.x;
    float wc[NH];
#pragma unroll
    for (int k = 0; k < NH; k++) wc[k] = Wh[k * 128 + j];
    __shared__ float hs[NH];
    __shared__ float gs[128];
    if (j < NH) hs[j] = 0.0f;
    float cst = 0.0f;
    __syncthreads();
    const float* gx = g_gx + ((size_t)dir * 4096 + b * NT) * 128;
    int t = dir ? (NT - 1) : 0;
    float gld = gx[t * 128 + j];
    for (int s = 0; s < NT; s++) {
        const int tn = dir ? (NT - 2 - s) : (s + 1);
        float gnext = (s < NT - 1) ? gx[tn * 128 + j] : 0.0f;  // prefetch
        float g0 = gld, g1 = 0.0f, g2 = 0.0f, g3 = 0.0f;
#pragma unroll
        for (int k = 0; k < NH; k += 4) {
            g0 += hs[k + 0] * wc[k + 0];
            g1 += hs[k + 1] * wc[k + 1];
            g2 += hs[k + 2] * wc[k + 2];
            g3 += hs[k + 3] * wc[k + 3];
        }
        gs[j] = (g0 + g1) + (g2 + g3);
        __syncthreads();
        if (j < NH) {
            float ig = 1.0f / (1.0f + __expf(-gs[j]));
            float fg = 1.0f / (1.0f + __expf(-gs[j + 32]));
            float gg = tanhf(gs[j + 64]);
            float og = 1.0f / (1.0f + __expf(-gs[j + 96]));
            cst = fg * cst + ig * gg;
            float hv = og * tanhf(cst);
            hs[j] = hv;
            g_hl[(size_t)(b * NT + t) * 64 + dir * NH + j] = hv;
        }
        __syncthreads();
        gld = gnext;
        t = tn;
    }
}

// ---------------- kernel 5: temporal attention + LN + MLP head ----------------
__global__ void k5(const float* __restrict__ taW, const float* __restrict__ tab,
                   const float* __restrict__ tav, const float* __restrict__ lng,
                   const float* __restrict__ lnb, const float* __restrict__ f1w,
                   const float* __restrict__ f1b, const float* __restrict__ f2w,
                   const float* __restrict__ f2b, float* __restrict__ out) {
    // grid NB, 256 threads (one per t)
    const int b = blockIdx.x, t = threadIdx.x;
    __shared__ float sW[64 * 64];
    __shared__ float sal[NT];
    __shared__ float wr[8];
    __shared__ float ctxs[64];
    __shared__ float y1s[32];
    __shared__ float stats[2];
    for (int i = t; i < 4096; i += 256) sW[i] = taW[i];
    float hrow[64];
    const float* hp = g_hl + (size_t)(b * NT + t) * 64;
#pragma unroll
    for (int k = 0; k < 64; k++) hrow[k] = hp[k];
    __syncthreads();
    float sc = 0.0f;
    for (int jj = 0; jj < 64; jj++) {
        float d = tab[jj];
#pragma unroll 8
        for (int k = 0; k < 64; k++) d += hrow[k] * sW[k * 64 + jj];
        sc += tanhf(d) * tav[jj];
    }
    sc *= (1.0f / 1.5f);
    // softmax over the 256 threads
    const int lane = t & 31, w = t >> 5;
    float m = sc;
#pragma unroll
    for (int o = 16; o; o >>= 1) m = fmaxf(m, __shfl_xor_sync(0xffffffffu, m, o));
    if (lane == 0) wr[w] = m;
    __syncthreads();
    m = wr[0];
#pragma unroll
    for (int i = 1; i < 8; i++) m = fmaxf(m, wr[i]);
    float e = __expf(sc - m);
    float s = e;
#pragma unroll
    for (int o = 16; o; o >>= 1) s += __shfl_xor_sync(0xffffffffu, s, o);
    __syncthreads();   // done reading wr (max) before overwrite
    if (lane == 0) wr[w] = s;
    __syncthreads();
    s = 0.0f;
#pragma unroll
    for (int i = 0; i < 8; i++) s += wr[i];
    sal[t] = e / s;
    __syncthreads();
    if (t < 64) {
        float cx = 0.0f;
        for (int tt = 0; tt < NT; tt++)
            cx += g_hl[(size_t)(b * NT + tt) * 64 + t] * sal[tt];
        ctxs[t] = cx;
    }
    __syncthreads();
    if (t == 0) {
        float mean = 0.0f;
        for (int k = 0; k < 64; k++) mean += ctxs[k];
        mean *= (1.0f / 64.0f);
        float var = 0.0f;
        for (int k = 0; k < 64; k++) { float d2 = ctxs[k] - mean; var += d2 * d2; }
        var *= (1.0f / 64.0f);
        stats[0] = mean;
        stats[1] = rsqrtf(var + 1e-5f);
    }
    __syncthreads();
    if (t < 64) ctxs[t] = (ctxs[t] - stats[0]) * stats[1] * lng[t] + lnb[t];
    __syncthreads();
    if (t < 32) {
        float a = f1b[t];
#pragma unroll
        for (int k = 0; k < 64; k++) a += ctxs[k] * f1w[k * 32 + t];
        y1s[t] = (a > 0.0f) ? a : 0.0f;
    }
    __syncthreads();
    if (t < 3) {
        float o = f2b[t];
#pragma unroll
        for (int m2 = 0; m2 < 32; m2++) o += y1s[m2] * f2w[m2 * 3 + t];
        out[b * 3 + t] = o;
    }
}

// ---------------- launcher ----------------
extern "C" void kernel_launch(void* const* d_in, const int* in_sizes, int n_in,
                              void* d_out, int out_size) {
    const float* x       = (const float*)d_in[0];
    const float* spec_w  = (const float*)d_in[1];
    const float* gat_W   = (const float*)d_in[2];
    const float* gat_a   = (const float*)d_in[3];
    const float* pool_w  = (const float*)d_in[4];
    const float* pool_b  = (const float*)d_in[5];
    const float* Wi_f    = (const float*)d_in[6];
    const float* Wh_f    = (const float*)d_in[7];
    const float* b_f     = (const float*)d_in[8];
    const float* Wi_r    = (const float*)d_in[9];
    const float* Wh_r    = (const float*)d_in[10];
    const float* b_r     = (const float*)d_in[11];
    const float* taW     = (const float*)d_in[12];
    const float* tab     = (const float*)d_in[13];
    const float* tav     = (const float*)d_in[14];
    const float* lng     = (const float*)d_in[15];
    const float* lnb     = (const float*)d_in[16];
    const float* f1w     = (const float*)d_in[17];
    const float* f1b     = (const float*)d_in[18];
    const float* f2w     = (const float*)d_in[19];
    const float* f2b     = (const float*)d_in[20];

    const int k1_smem = (64 * 132 + 128 * 32 + 64) * 4;  // 50432 B
    cudaFuncSetAttribute(k1, cudaFuncAttributeMaxDynamicSharedMemorySize, k1_smem);

    k_sm<<<64, 128>>>(spec_w);
    k_zeroA<<<(NB * NC * NC + 255) / 256, 256>>>();
    k1<<<NB * (NT / TCHUNK), 256, k1_smem>>>(x, gat_W, gat_a);
    k2<<<NB, 64>>>();
    k3<<<NB * NT, 256>>>(pool_w, pool_b);
    k4a<<<2 * NB * NT, 128>>>(Wi_f, b_f, Wi_r, b_r);
    k4b<<<32, 128>>>(Wh_f, Wh_r);
    k5<<<NB, 256>>>(taW, tab, tav, lng, lnb, f1w, f1b, f2w, f2b, (float*)d_out);
}

// round 2
// speedup vs baseline: 1.1557x; 1.1557x over previous
#include <cuda_runtime.h>
#include <math.h>

#define NB 16
#define NT 256
#define NC 64
#define NF 128
#define NGO 32
#define NH 32
#define TCHUNK 8

// ---------------- packed f32x2 helpers ----------------
__device__ __forceinline__ unsigned long long PK(float x, float y) {
    unsigned long long r;
    asm("mov.b64 %0, {%1,%2};" : "=l"(r) : "f"(x), "f"(y));
    return r;
}
__device__ __forceinline__ float2 UPK(unsigned long long v) {
    float2 f;
    asm("mov.b64 {%0,%1}, %2;" : "=f"(f.x), "=f"(f.y) : "l"(v));
    return f;
}
__device__ __forceinline__ unsigned long long FFMA2(unsigned long long a,
                                                    unsigned long long b,
                                                    unsigned long long c) {
    unsigned long long d;
    asm("fma.rn.f32x2 %0, %1, %2, %3;" : "=l"(d) : "l"(a), "l"(b), "l"(c));
    return d;
}
__device__ __forceinline__ float HSUM(unsigned long long v) {
    float2 f = UPK(v);
    return f.x + f.y;
}
__device__ __forceinline__ float fast_tanh(float x) {
    float e = __expf(2.0f * x);
    return 1.0f - __fdividef(2.0f, e + 1.0f);
}
__device__ __forceinline__ float fast_sig(float x) {
    return 1.0f / (1.0f + __expf(-x));
}

// ---------------- scratch (device globals; no allocation) ----------------
__device__ float g_sm[NC * NF];
__device__ float g_A[NB * NC * NC];
__device__ unsigned long long g_um[NB * NC];
__device__ unsigned char g_amask[NB * NC * NC];
__device__ float g_Wh[NB * NT * NC * NGO];
__device__ float g_s1[NB * NT * NC];
__device__ float g_s2[NB * NT * NC];
__device__ float g_hp[NB * NT * NH];
__device__ float g_gx[2 * NB * NT * 4 * NH];
__device__ float g_hl[NB * NT * 2 * NH];
__device__ float g_sc[NB * NT];

// ---------------- kernel 0: row softmax of spectral_w ----------------
__global__ void k_sm(const float* __restrict__ sw) {
    int c = blockIdx.x, f = threadIdx.x;
    float v = sw[c * NF + f];
    __shared__ float rm[4], rs[4];
    int lane = f & 31, w = f >> 5;
    float m = v;
#pragma unroll
    for (int o = 16; o; o >>= 1) m = fmaxf(m, __shfl_xor_sync(0xffffffffu, m, o));
    if (lane == 0) rm[w] = m;
    __syncthreads();
    m = fmaxf(fmaxf(rm[0], rm[1]), fmaxf(rm[2], rm[3]));
    float e = __expf(v - m);
    float s = e;
#pragma unroll
    for (int o = 16; o; o >>= 1) s += __shfl_xor_sync(0xffffffffu, s, o);
    if (lane == 0) rs[w] = s;
    __syncthreads();
    s = rs[0] + rs[1] + rs[2] + rs[3];
    g_sm[c * NF + f] = e / s;
}

__global__ void k_zeroA() {
    int i = blockIdx.x * blockDim.x + threadIdx.x;
    if (i < NB * NC * NC) g_A[i] = 0.0f;
}

// ---------------- kernel 1: spectral weight + Gram->A + Wh + s1/s2 ----------------
extern __shared__ float sh1[];
__global__ void k1(const float* __restrict__ x,
                   const float* __restrict__ gatW,
                   const float* __restrict__ gata) {
    float* xw   = sh1;                    // 64*132
    float* sw   = sh1 + 64 * 132;         // 128*32
    float* invn = sw + 128 * 32;          // 64

    const int b  = blockIdx.x / (NT / TCHUNK);
    const int t0 = (blockIdx.x % (NT / TCHUNK)) * TCHUNK;
    const int tid = threadIdx.x;

    for (int i = tid; i < NF * NGO; i += 256) sw[i] = gatW[i];

    // triangle 4x4-tile mapping (136 tiles of 256 threads)
    int ci = -1, di = -1;
    {
        int u = tid;
        for (int r = 0; r < 16; r++) {
            int len = 16 - r;
            if (u < len) { ci = r; di = r + u; break; }
            u -= len;
        }
        if (tid >= 136) ci = -1;
    }
    const int r0 = (ci >= 0) ? ci * 4 : 0;
    const int c0 = (ci >= 0) ? di * 4 : 0;

    const int cW = tid >> 2, q = tid & 3, o0 = q * 8;
    float ga1[8], ga2[8];
#pragma unroll
    for (int i = 0; i < 8; i++) { ga1[i] = gata[o0 + i]; ga2[i] = gata[NGO + o0 + i]; }

    float acc[16];
#pragma unroll
    for (int i = 0; i < 16; i++) acc[i] = 0.0f;

    for (int tt = 0; tt < TCHUNK; tt++) {
        const int t = t0 + tt;
        const float* xp = x + ((size_t)(b * NT + t)) * NC * NF;
        __syncthreads();
        for (int i = tid * 4; i < NC * NF; i += 1024) {
            float4 v = *(const float4*)(xp + i);
            float4 s = *(const float4*)(g_sm + i);
            int c = i >> 7, f = i & 127;
            float* dst = &xw[c * 132 + f];
            dst[0] = v.x * s.x; dst[1] = v.y * s.y; dst[2] = v.z * s.z; dst[3] = v.w * s.w;
        }
        __syncthreads();
        if (tid < 64) {
            unsigned long long n2 = 0ull;
            const float* row = &xw[tid * 132];
#pragma unroll 8
            for (int f = 0; f < NF; f += 4) {
                float4 a = *(const float4*)(row + f);
                n2 = FFMA2(PK(a.x, a.y), PK(a.x, a.y), n2);
                n2 = FFMA2(PK(a.z, a.w), PK(a.z, a.w), n2);
            }
            invn[tid] = 1.0f / (sqrtf(HSUM(n2)) + 1e-8f);
        }
        // Wh (packed): thread = (cW, outputs o0..o0+7)
        {
            unsigned long long wa2[4] = {0ull, 0ull, 0ull, 0ull};
            const float* xrow = &xw[cW * 132];
#pragma unroll 4
            for (int f = 0; f < NF; f++) {
                float xv = xrow[f];
                unsigned long long xx = PK(xv, xv);
                float4 w0 = *(const float4*)&sw[f * NGO + o0];
                float4 w1 = *(const float4*)&sw[f * NGO + o0 + 4];
                wa2[0] = FFMA2(xx, PK(w0.x, w0.y), wa2[0]);
                wa2[1] = FFMA2(xx, PK(w0.z, w0.w), wa2[1]);
                wa2[2] = FFMA2(xx, PK(w1.x, w1.y), wa2[2]);
                wa2[3] = FFMA2(xx, PK(w1.z, w1.w), wa2[3]);
            }
            float wa[8];
#pragma unroll
            for (int i = 0; i < 4; i++) {
                float2 v2 = UPK(wa2[i]);
                wa[2 * i] = v2.x; wa[2 * i + 1] = v2.y;
            }
            float* whp = g_Wh + (((size_t)(b * NT + t) * NC + cW) * NGO + o0);
            *(float4*)whp       = make_float4(wa[0], wa[1], wa[2], wa[3]);
            *(float4*)(whp + 4) = make_float4(wa[4], wa[5], wa[6], wa[7]);
            float p1 = 0.0f, p2 = 0.0f;
#pragma unroll
            for (int i = 0; i < 8; i++) { p1 += wa[i] * ga1[i]; p2 += wa[i] * ga2[i]; }
            p1 += __shfl_xor_sync(0xffffffffu, p1, 1);
            p1 += __shfl_xor_sync(0xffffffffu, p1, 2);
            p2 += __shfl_xor_sync(0xffffffffu, p2, 1);
            p2 += __shfl_xor_sync(0xffffffffu, p2, 2);
            if (q == 0) {
                g_s1[(size_t)(b * NT + t) * NC + cW] = p1;
                g_s2[(size_t)(b * NT + t) * NC + cW] = p2;
            }
        }
        __syncthreads();
        // Gram tile (packed)
        if (ci >= 0) {
            unsigned long long tm2[16];
#pragma unroll
            for (int i = 0; i < 16; i++) tm2[i] = 0ull;
            for (int k = 0; k < NF; k += 4) {
                float4 a0 = *(const float4*)&xw[(r0 + 0) * 132 + k];
                float4 a1 = *(const float4*)&xw[(r0 + 1) * 132 + k];
                float4 a2 = *(const float4*)&xw[(r0 + 2) * 132 + k];
                float4 a3 = *(const float4*)&xw[(r0 + 3) * 132 + k];
                float4 b0 = *(const float4*)&xw[(c0 + 0) * 132 + k];
                float4 b1 = *(const float4*)&xw[(c0 + 1) * 132 + k];
                float4 b2 = *(const float4*)&xw[(c0 + 2) * 132 + k];
                float4 b3 = *(const float4*)&xw[(c0 + 3) * 132 + k];
#define GPAIR(IDX, AV, BV) \
    tm2[IDX] = FFMA2(PK(AV.x, AV.y), PK(BV.x, BV.y), tm2[IDX]); \
    tm2[IDX] = FFMA2(PK(AV.z, AV.w), PK(BV.z, BV.w), tm2[IDX]);
                GPAIR(0,  a0, b0) GPAIR(1,  a0, b1) GPAIR(2,  a0, b2) GPAIR(3,  a0, b3)
                GPAIR(4,  a1, b0) GPAIR(5,  a1, b1) GPAIR(6,  a1, b2) GPAIR(7,  a1, b3)
                GPAIR(8,  a2, b0) GPAIR(9,  a2, b1) GPAIR(10, a2, b2) GPAIR(11, a2, b3)
                GPAIR(12, a3, b0) GPAIR(13, a3, b1) GPAIR(14, a3, b2) GPAIR(15, a3, b3)
#undef GPAIR
            }
            float ir[4], ic[4];
#pragma unroll
            for (int i = 0; i < 4; i++) { ir[i] = invn[r0 + i]; ic[i] = invn[c0 + i]; }
#pragma unroll
            for (int r = 0; r < 4; r++)
#pragma unroll
                for (int cc = 0; cc < 4; cc++)
                    acc[r * 4 + cc] += HSUM(tm2[r * 4 + cc]) * ir[r] * ic[cc];
        }
    }
    if (ci >= 0) {
        float* Ab = g_A + b * NC * NC;
#pragma unroll
        for (int r = 0; r < 4; r++)
#pragma unroll
            for (int cc = 0; cc < 4; cc++) {
                float v = acc[r * 4 + cc];
                atomicAdd(&Ab[(r0 + r) * NC + (c0 + cc)], v);
                if (ci != di) atomicAdd(&Ab[(c0 + cc) * NC + (r0 + r)], v);
            }
    }
}

// ---------------- kernel 2a: per-row top-4 via warp argmax ----------------
__global__ void k2a() {  // grid 128 blocks x 256 threads = 1024 warps... (8 warps/blk)
    int warp = blockIdx.x * 8 + (threadIdx.x >> 5);   // 0..1023
    int b = warp >> 6, row = warp & 63;
    int lane = threadIdx.x & 31;
    const float* Ar = g_A + ((size_t)b * NC + row) * NC;
    float v0 = Ar[lane], v1 = Ar[lane + 32];
    unsigned long long mask = 0ull;
#pragma unroll
    for (int r = 0; r < 4; r++) {
        float best; int bi;
        if (v1 > v0) { best = v1; bi = lane + 32; } else { best = v0; bi = lane; }
#pragma unroll
        for (int o = 16; o; o >>= 1) {
            float ov = __shfl_xor_sync(0xffffffffu, best, o);
            int oi = __shfl_xor_sync(0xffffffffu, bi, o);
            if (ov > best || (ov == best && oi < bi)) { best = ov; bi = oi; }
        }
        mask |= 1ull << bi;
        if (bi == lane) v0 = -3.4e38f;
        if (bi == lane + 32) v1 = -3.4e38f;
    }
    mask &= ~(1ull << row);
    if (lane == 0) g_um[b * NC + row] = mask;
}

// ---------------- kernel 2b: build amask ----------------
__global__ void k2b() {  // grid NB, 1024 threads
    __shared__ unsigned long long um[NC];
    const int b = blockIdx.x, tid = threadIdx.x;
    if (tid < NC) um[tid] = g_um[b * NC + tid];
    __syncthreads();
    const float* Ab = g_A + (size_t)b * NC * NC;
    unsigned char* amp = g_amask + (size_t)b * NC * NC;
#pragma unroll
    for (int i = tid; i < NC * NC; i += 1024) {
        int c = i >> 6, d = i & 63;
        bool tk = (((um[c] >> d) | (um[d] >> c)) & 1ull) != 0;
        amp[i] = ((tk && Ab[i] > 0.0f) || (c == d)) ? 1 : 0;
    }
}

// ---------------- kernel 3: GAT attention + node pooling ----------------
__global__ void k3(const float* __restrict__ pool_w, const float* __restrict__ pool_b) {
    __shared__ __align__(16) float sWh[NC * NGO];
    __shared__ float sp[NC * 65];
    __shared__ float sgat[NC * 33];
    __shared__ float ss1[NC], ss2[NC], rinv[NC], pnum[NC];
    __shared__ float pw[NGO];
    __shared__ unsigned int samw[NC * NC / 4];
    unsigned char* sam = (unsigned char*)samw;

    const int bt = blockIdx.x;
    const int b = bt >> 8;
    const int tid = threadIdx.x;

    const float* whp = g_Wh + (size_t)bt * NC * NGO;
    for (int i = tid; i < NC * NGO; i += 256) sWh[i] = whp[i];
    if (tid < NC) {
        ss1[tid] = g_s1[(size_t)bt * NC + tid];
        ss2[tid] = g_s2[(size_t)bt * NC + tid];
    }
    const unsigned int* amp = (const unsigned int*)(g_amask + (size_t)b * NC * NC);
    for (int i = tid; i < NC * NC / 4; i += 256) samw[i] = amp[i];
    if (tid < NGO) pw[tid] = pool_w[tid];
    __syncthreads();

    const int c = tid >> 2, q = tid & 3, d0 = q * 16;
    float ev[16];
    float m = -3.4e38f;
    const float s1c = ss1[c];
#pragma unroll
    for (int i = 0; i < 16; i++) {
        int d = d0 + i;
        float e = s1c + ss2[d];
        e = (e >= 0.0f) ? e : 0.2f * e;
        if (!sam[c * NC + d]) e = -1e9f;
        ev[i] = e;
        m = fmaxf(m, e);
    }
    m = fmaxf(m, __shfl_xor_sync(0xffffffffu, m, 1));
    m = fmaxf(m, __shfl_xor_sync(0xffffffffu, m, 2));
    float s = 0.0f;
#pragma unroll
    for (int i = 0; i < 16; i++) {
        float p = __expf(ev[i] - m);
        sp[c * 65 + d0 + i] = p;
        s += p;
    }
    s += __shfl_xor_sync(0xffffffffu, s, 1);
    s += __shfl_xor_sync(0xffffffffu, s, 2);
    if (q == 0) rinv[c] = 1.0f / s;
    __syncthreads();

    // phase B: packed alpha @ Wh
    const int o0 = q * 8;
    unsigned long long a2[4] = {0ull, 0ull, 0ull, 0ull};
    for (int d = 0; d < NC; d++) {
        float al = sp[c * 65 + d];
        unsigned long long aa = PK(al, al);
        float4 w0 = *(const float4*)&sWh[d * NGO + o0];
        float4 w1 = *(const float4*)&sWh[d * NGO + o0 + 4];
        a2[0] = FFMA2(aa, PK(w0.x, w0.y), a2[0]);
        a2[1] = FFMA2(aa, PK(w0.z, w0.w), a2[1]);
        a2[2] = FFMA2(aa, PK(w1.x, w1.y), a2[2]);
        a2[3] = FFMA2(aa, PK(w1.z, w1.w), a2[3]);
    }
    const float ri = rinv[c];
#pragma unroll
    for (int i = 0; i < 4; i++) {
        float2 v2 = UPK(a2[i]);
        float g0 = v2.x * ri, g1 = v2.y * ri;
        sgat[c * 33 + o0 + 2 * i]     = (g0 > 0.0f) ? g0 : 0.0f;
        sgat[c * 33 + o0 + 2 * i + 1] = (g1 > 0.0f) ? g1 : 0.0f;
    }
    __syncthreads();

    if (tid < NC) {
        float p = pool_b[0];
#pragma unroll
        for (int o = 0; o < NGO; o++) p += sgat[tid * 33 + o] * pw[o];
        pnum[tid] = p;
    }
    __syncthreads();
    if (tid < 32) {
        float a0 = pnum[tid], a1 = pnum[tid + 32];
        float mx = fmaxf(a0, a1);
#pragma unroll
        for (int o = 16; o; o >>= 1) mx = fmaxf(mx, __shfl_xor_sync(0xffffffffu, mx, o));
        float e0 = __expf(a0 - mx), e1 = __expf(a1 - mx);
        float sm = e0 + e1;
#pragma unroll
        for (int o = 16; o; o >>= 1) sm += __shfl_xor_sync(0xffffffffu, sm, o);
        pnum[tid] = e0 / sm;
        pnum[tid + 32] = e1 / sm;
    }
    __syncthreads();
    if (tid < NGO) {
        float hv = 0.0f;
#pragma unroll 4
        for (int c2 = 0; c2 < NC; c2++) hv += sgat[c2 * 33 + tid] * pnum[c2];
        g_hp[(size_t)bt * NH + tid] = hv;
    }
}

// ---------------- kernel 4a: LSTM input gates ----------------
__global__ void k4a(const float* __restrict__ Wi_f, const float* __restrict__ b_f,
                    const float* __restrict__ Wi_r, const float* __restrict__ b_r) {
    const int id = blockIdx.x;
    const int dir = id >> 12;
    const int bt = id & 4095;
    const float* Wi = dir ? Wi_r : Wi_f;
    const float* bias = dir ? b_r : b_f;
    __shared__ float hr[NH];
    if (threadIdx.x < NH) hr[threadIdx.x] = g_hp[(size_t)bt * NH + threadIdx.x];
    __syncthreads();
    const int j = threadIdx.x;
    float a = bias[j];
#pragma unroll
    for (int k = 0; k < NH; k++) a += hr[k] * Wi[k * 128 + j];
    g_gx[((size_t)dir * 4096 + bt) * 128 + j] = a;
}

// ---------------- kernel 4b: LSTM recurrence (1 warp / (dir,b), no barriers) ----------------
__global__ void __launch_bounds__(32) k4b(const float* __restrict__ Wh_f,
                                          const float* __restrict__ Wh_r) {
    const int dir = blockIdx.x >> 4;
    const int b = blockIdx.x & 15;
    const float* Wh = dir ? Wh_r : Wh_f;
    const int j = threadIdx.x;
    unsigned long long wif[NH], wgo[NH];
#pragma unroll
    for (int k = 0; k < NH; k++) {
        const float* r = Wh + k * 128;
        wif[k] = PK(r[j], r[j + 32]);
        wgo[k] = PK(r[j + 64], r[j + 96]);
    }
    const float* gx = g_gx + ((size_t)dir * 4096 + b * NT) * 128;
    float h = 0.0f, cst = 0.0f;
    int t = dir ? (NT - 1) : 0;
    const int st = dir ? -1 : 1;
    const float* g0p = gx + t * 128;
    float c0 = g0p[j], c1 = g0p[j + 32], c2 = g0p[j + 64], c3 = g0p[j + 96];
    for (int s = 0; s < NT; s++) {
        const int tn = t + st;
        float n0 = 0.0f, n1 = 0.0f, n2 = 0.0f, n3 = 0.0f;
        if (s < NT - 1) {
            const float* gn = gx + tn * 128;
            n0 = gn[j]; n1 = gn[j + 32]; n2 = gn[j + 64]; n3 = gn[j + 96];
        }
        unsigned long long aIF  = PK(c0, c1), aGO  = PK(c2, c3);
        unsigned long long aIF2 = 0ull,      aGO2 = 0ull;
#pragma unroll
        for (int k = 0; k < NH; k += 2) {
            float hk0 = __shfl_sync(0xffffffffu, h, k);
            float hk1 = __shfl_sync(0xffffffffu, h, k + 1);
            unsigned long long hh0 = PK(hk0, hk0), hh1 = PK(hk1, hk1);
            aIF  = FFMA2(hh0, wif[k],     aIF);
            aGO  = FFMA2(hh0, wgo[k],     aGO);
            aIF2 = FFMA2(hh1, wif[k + 1], aIF2);
            aGO2 = FFMA2(hh1, wgo[k + 1], aGO2);
        }
        float2 vIF = UPK(aIF), vIF2 = UPK(aIF2), vGO = UPK(aGO), vGO2 = UPK(aGO2);
        float gi = vIF.x + vIF2.x, gf = vIF.y + vIF2.y;
        float gg = vGO.x + vGO2.x, go = vGO.y + vGO2.y;
        float ig = fast_sig(gi), fg = fast_sig(gf), og = fast_sig(go);
        cst = fg * cst + ig * fast_tanh(gg);
        h = og * fast_tanh(cst);
        g_hl[(size_t)(b * NT + t) * 64 + dir * NH + j] = h;
        c0 = n0; c1 = n1; c2 = n2; c3 = n3;
        t = tn;
    }
}

// ---------------- kernel 5a: temporal attention scores ----------------
__global__ void k5a(const float* __restrict__ taW, const float* __restrict__ tab,
                    const float* __restrict__ tav) {
    // grid 64 (b = blk>>2, quarter of t), 64 threads
    __shared__ float sWt[64 * 65];  // transposed
    __shared__ float stb[64], stv[64];
    const int tid = threadIdx.x;
    for (int i = tid; i < 4096; i += 64) {
        int k = i >> 6, jj = i & 63;
        sWt[jj * 65 + k] = taW[i];
    }
    if (tid < 64) { stb[tid] = tab[tid]; stv[tid] = tav[tid]; }
    __syncthreads();
    const int b = blockIdx.x >> 2;
    const int t = (blockIdx.x & 3) * 64 + tid;
    const float* hp = g_hl + (size_t)(b * NT + t) * 64;
    float h[64];
#pragma unroll
    for (int k = 0; k < 64; k += 4) {
        float4 v = *(const float4*)(hp + k);
        h[k] = v.x; h[k + 1] = v.y; h[k + 2] = v.z; h[k + 3] = v.w;
    }
    float sc = 0.0f;
    for (int jj = 0; jj < 64; jj++) {
        unsigned long long a0 = PK(stb[jj], 0.0f), a1 = 0ull;
        const float* wr = &sWt[jj * 65];
#pragma unroll
        for (int k = 0; k < 64; k += 4) {
            a0 = FFMA2(PK(h[k], h[k + 1]), PK(wr[k], wr[k + 1]), a0);
            a1 = FFMA2(PK(h[k + 2], h[k + 3]), PK(wr[k + 2], wr[k + 3]), a1);
        }
        sc += fast_tanh(HSUM(a0) + HSUM(a1)) * stv[jj];
    }
    g_sc[b * NT + t] = sc * (1.0f / 1.5f);
}

// ---------------- kernel 5b: softmax + ctx + LN + MLP head ----------------
__global__ void k5b(const float* __restrict__ lng, const float* __restrict__ lnb,
                    const float* __restrict__ f1w, const float* __restrict__ f1b,
                    const float* __restrict__ f2w, const float* __restrict__ f2b,
                    float* __restrict__ out) {
    const int b = blockIdx.x, t = threadIdx.x;
    __shared__ float sal[NT];
    __shared__ float wr[8];
    __shared__ float part[4][64];
    __shared__ float ctxs[64];
    __shared__ float y1s[32];
    __shared__ float stats[2];
    float sc = g_sc[b * NT + t];
    const int lane = t & 31, w = t >> 5;
    float m = sc;
#pragma unroll
    for (int o = 16; o; o >>= 1) m = fmaxf(m, __shfl_xor_sync(0xffffffffu, m, o));
    if (lane == 0) wr[w] = m;
    __syncthreads();
    m = wr[0];
#pragma unroll
    for (int i = 1; i < 8; i++) m = fmaxf(m, wr[i]);
    float e = __expf(sc - m);
    float s = e;
#pragma unroll
    for (int o = 16; o; o >>= 1) s += __shfl_xor_sync(0xffffffffu, s, o);
    __syncthreads();
    if (lane == 0) wr[w] = s;
    __syncthreads();
    s = 0.0f;
#pragma unroll
    for (int i = 0; i < 8; i++) s += wr[i];
    sal[t] = e / s;
    __syncthreads();
    // ctx: thread = (quarter q4 of tt, feature k)
    {
        const int k = t & 63, q4 = t >> 6;
        float cx = 0.0f;
        const float* hb = g_hl + (size_t)b * NT * 64;
        for (int tt = q4 * 64; tt < q4 * 64 + 64; tt++)
            cx += hb[(size_t)tt * 64 + k] * sal[tt];
        part[q4][k] = cx;
    }
    __syncthreads();
    if (t < 64) ctxs[t] = part[0][t] + part[1][t] + part[2][t] + part[3][t];
    __syncthreads();
    if (t == 0) {
        float mean = 0.0f;
        for (int k = 0; k < 64; k++) mean += ctxs[k];
        mean *= (1.0f / 64.0f);
        float var = 0.0f;
        for (int k = 0; k < 64; k++) { float d2 = ctxs[k] - mean; var += d2 * d2; }
        var *= (1.0f / 64.0f);
        stats[0] = mean;
        stats[1] = rsqrtf(var + 1e-5f);
    }
    __syncthreads();
    if (t < 64) ctxs[t] = (ctxs[t] - stats[0]) * stats[1] * lng[t] + lnb[t];
    __syncthreads();
    if (t < 32) {
        float a = f1b[t];
#pragma unroll
        for (int k = 0; k < 64; k++) a += ctxs[k] * f1w[k * 32 + t];
        y1s[t] = (a > 0.0f) ? a : 0.0f;
    }
    __syncthreads();
    if (t < 3) {
        float o = f2b[t];
#pragma unroll
        for (int m2 = 0; m2 < 32; m2++) o += y1s[m2] * f2w[m2 * 3 + t];
        out[b * 3 + t] = o;
    }
}

// ---------------- launcher ----------------
extern "C" void kernel_launch(void* const* d_in, const int* in_sizes, int n_in,
                              void* d_out, int out_size) {
    const float* x       = (const float*)d_in[0];
    const float* spec_w  = (const float*)d_in[1];
    const float* gat_W   = (const float*)d_in[2];
    const float* gat_a   = (const float*)d_in[3];
    const float* pool_w  = (const float*)d_in[4];
    const float* pool_b  = (const float*)d_in[5];
    const float* Wi_f    = (const float*)d_in[6];
    const float* Wh_f    = (const float*)d_in[7];
    const float* b_f     = (const float*)d_in[8];
    const float* Wi_r    = (const float*)d_in[9];
    const float* Wh_r    = (const float*)d_in[10];
    const float* b_r     = (const float*)d_in[11];
    const float* taW     = (const float*)d_in[12];
    const float* tab     = (const float*)d_in[13];
    const float* tav     = (const float*)d_in[14];
    const float* lng     = (const float*)d_in[15];
    const float* lnb     = (const float*)d_in[16];
    const float* f1w     = (const float*)d_in[17];
    const float* f1b     = (const float*)d_in[18];
    const float* f2w     = (const float*)d_in[19];
    const float* f2b     = (const float*)d_in[20];

    const int k1_smem = (64 * 132 + 128 * 32 + 64) * 4;
    cudaFuncSetAttribute(k1, cudaFuncAttributeMaxDynamicSharedMemorySize, k1_smem);

    k_sm<<<64, 128>>>(spec_w);
    k_zeroA<<<(NB * NC * NC + 255) / 256, 256>>>();
    k1<<<NB * (NT / TCHUNK), 256, k1_smem>>>(x, gat_W, gat_a);
    k2a<<<128, 256>>>();
    k2b<<<NB, 1024>>>();
    k3<<<NB * NT, 256>>>(pool_w, pool_b);
    k4a<<<2 * NB * NT, 128>>>(Wi_f, b_f, Wi_r, b_r);
    k4b<<<32, 32>>>(Wh_f, Wh_r);
    k5a<<<64, 64>>>(taW, tab, tav);
    k5b<<<NB, 256>>>(lng, lnb, f1w, f1b, f2w, f2b, (float*)d_out);
}